// round 6
// baseline (speedup 1.0000x reference)
#include <cuda_runtime.h>
#include <cuda_fp16.h>
#include <math.h>

#define NN   30000
#define EE   480000
#define HH   128
#define NFF  4
#define NMM  8
#define TT   4
#define DMID 8
#define KCAT 132
#define KC   64
#define BM   64          // fused tile: nodes per block
#define EPSF 1e-5f
#define DTF  0.1f

#define FUSED_SMEM (64 * HH * 8 + BM * HH * 4)   // 64KB packed W + 32KB zs = 98304

typedef unsigned long long ull;

// ---------------- scratch (static device memory; no allocations) ----------------
__device__ int    g_cnt[NN];
__device__ float  g_dinv[NN];
__device__ int    g_rowptr[NN + 1];
__device__ int    g_cursor[NN];
__device__ int2   g_edge[EE + 8];      // {src, bits(dinv[src]*dinv[dst])}; +8 pad
__device__ float  g_x[NN * HH];
__device__ float  g_z[NN * HH];
__device__ __half g_xh0[NN * HH];      // half activation ping
__device__ __half g_xh1[NN * HH];      // half activation pong
__device__ float  g_xcat[NN * KCAT];   // [aggF(4) | agg_mesh(128)]
__device__ float  g_small[NN * NMM];   // aggregated meshfield (8 cols)
__device__ float  g_F[NN * NFF];
__device__ float  g_h4[NN * NFF];
__device__ float  g_stats[2 * HH];
__device__ float  g_nm[HH];            // per-channel mean
__device__ float  g_nr[HH];            // per-channel rstd

// ---------------- packed fp32 helpers ----------------
__device__ __forceinline__ ull pk2(float lo, float hi) {
    ull o; asm("mov.b64 %0, {%1, %2};" : "=l"(o) : "f"(lo), "f"(hi)); return o;
}
__device__ __forceinline__ void upk2(float& lo, float& hi, ull v) {
    asm("mov.b64 {%0, %1}, %2;" : "=f"(lo), "=f"(hi) : "l"(v));
}
__device__ __forceinline__ ull ffma2(ull a, ull b, ull c) {
    ull d; asm("fma.rn.f32x2 %0, %1, %2, %3;" : "=l"(d) : "l"(a), "l"(b), "l"(c)); return d;
}

// row loader: fp32 (512B rows) or fp16 (256B rows), returns this lane's 4 cols
template <bool INH>
__device__ __forceinline__ float4 ldrow(const void* in, int s, int lane) {
    if (INH) {
        uint2 u = ((const uint2*)in)[(size_t)s * 32 + lane];
        float2 a = __half22float2(*(const __half2*)&u.x);
        float2 b = __half22float2(*(const __half2*)&u.y);
        return make_float4(a.x, a.y, b.x, b.y);
    } else {
        return ((const float4*)in)[(size_t)s * 32 + lane];
    }
}

// ---------------- graph normalization + CSR build ----------------
__global__ void k_zero_cnt() {
    int i = blockIdx.x * blockDim.x + threadIdx.x;
    if (i < NN) g_cnt[i] = 0;
    if (i < 8) g_edge[EE + i] = make_int2(0, 0);
}
__global__ void k_count(const int* __restrict__ ei) {
    int e = blockIdx.x * blockDim.x + threadIdx.x;
    if (e < EE) atomicAdd(&g_cnt[ei[EE + e]], 1);
}
__global__ void k_dinv() {
    int i = blockIdx.x * blockDim.x + threadIdx.x;
    if (i < NN) g_dinv[i] = rsqrtf((float)g_cnt[i] + 1.0f);  // deg includes self loop
}
__global__ void k_scan() {
    __shared__ int partial[1024];
    const int CH = (NN + 1023) / 1024;
    int tid = threadIdx.x;
    int base = tid * CH;
    int s = 0;
    for (int j = 0; j < CH; j++) {
        int idx = base + j;
        if (idx < NN) s += g_cnt[idx];
    }
    partial[tid] = s;
    __syncthreads();
    for (int off = 1; off < 1024; off <<= 1) {
        int v = (tid >= off) ? partial[tid - off] : 0;
        __syncthreads();
        partial[tid] += v;
        __syncthreads();
    }
    int run = partial[tid] - s;  // exclusive prefix
    for (int j = 0; j < CH; j++) {
        int idx = base + j;
        if (idx < NN) {
            g_rowptr[idx] = run;
            g_cursor[idx] = run;
            run += g_cnt[idx];
        }
    }
    if (tid == 1023) g_rowptr[NN] = partial[1023];
}
__global__ void k_fill(const int* __restrict__ ei) {
    int e = blockIdx.x * blockDim.x + threadIdx.x;
    if (e < EE) {
        int s = ei[e];
        int d = ei[EE + e];
        int p = atomicAdd(&g_cursor[d], 1);
        g_edge[p] = make_int2(s, __float_as_int(g_dinv[s] * g_dinv[d]));
    }
}

// ---------------- FUSED [norm] -> agg(+relu) -> GEMM(K=128) (+bias, opt tanh) -----
// Full k-pair-packed W staged in smem once (one __syncthreads). Each warp then:
// gather its 8 rows (fp16 or fp32 input) -> __syncwarp -> per-warp GEMM.
// Output fp16 (inter-layer) or fp32 (pre-aggregate latent).
template <bool NORM, bool RELU, int ACT, bool INH, bool OUTH>
__global__ void __launch_bounds__(256)
k_fused(const void* __restrict__ in, const float* __restrict__ W,
        const float* __restrict__ bias, void* __restrict__ out) {
    extern __shared__ char smem[];
    ull*   wp = (ull*)smem;                       // 64 k-pairs x 128 cols (64 KB)
    float* zs = (float*)(smem + 64 * HH * 8);     // 64 rows x 128 cols (32 KB)

    int tid = threadIdx.x;
    int lane = tid & 31, wrp = tid >> 5;
    int row0 = blockIdx.x * BM;
    const int2* ge = g_edge;

    // ---- stage full W as even/odd k-pairs: wp[p][c] = (W[2p][c], W[2p+1][c]) ----
    {
        int c4 = lane * 4;
#pragma unroll
        for (int rep = 0; rep < 8; rep++) {
            int pr = wrp + 8 * rep;               // 0..63
            float4 r0 = *(const float4*)&W[(size_t)(2 * pr) * HH + c4];
            float4 r1 = *(const float4*)&W[(size_t)(2 * pr + 1) * HH + c4];
            *(ulonglong2*)&wp[pr * HH + c4]     = make_ulonglong2(pk2(r0.x, r1.x), pk2(r0.y, r1.y));
            *(ulonglong2*)&wp[pr * HH + c4 + 2] = make_ulonglong2(pk2(r0.z, r1.z), pk2(r0.w, r1.w));
        }
    }

    float4 m4, r4;
    if (NORM) {
        m4 = ((const float4*)g_nm)[lane];
        r4 = ((const float4*)g_nr)[lane];
    }
    __syncthreads();   // the ONLY block-wide sync

    // ---- Phase A (per-warp): gather 8 rows into this warp's zs slice ----
    for (int mi = 0; mi < 8; mi++) {
        int m = wrp * 8 + mi;
        int i = row0 + m;
        if (i >= NN) break;
        float di = g_dinv[i];

#define LOADU(u, s)                                                        \
        float4 u = ldrow<INH>(in, (s), lane);                              \
        if (NORM) { u.x = (u.x - m4.x) * r4.x; u.y = (u.y - m4.y) * r4.y;  \
                    u.z = (u.z - m4.z) * r4.z; u.w = (u.w - m4.w) * r4.w; }\
        if (RELU) { u.x = fmaxf(u.x, 0.f); u.y = fmaxf(u.y, 0.f);          \
                    u.z = fmaxf(u.z, 0.f); u.w = fmaxf(u.w, 0.f); }

        LOADU(vs, i)
        float w = di * di;
        float p0 = w * vs.x, p1 = w * vs.y, p2 = w * vs.z, p3 = w * vs.w;
        float q0 = 0.f, q1 = 0.f, q2 = 0.f, q3 = 0.f;
        int e = g_rowptr[i], end = g_rowptr[i + 1];
        int2 h0 = ge[e], h1 = ge[e + 1], h2 = ge[e + 2], h3 = ge[e + 3];
        for (; e + 4 <= end; e += 4) {
            int2 n0 = ge[e + 4], n1 = ge[e + 5], n2 = ge[e + 6], n3 = ge[e + 7];
            float w0 = __int_as_float(h0.y), w1 = __int_as_float(h1.y);
            float w2 = __int_as_float(h2.y), w3 = __int_as_float(h3.y);
            LOADU(u0, h0.x) LOADU(u1, h1.x) LOADU(u2, h2.x) LOADU(u3, h3.x)
            p0 += w0 * u0.x; p1 += w0 * u0.y; p2 += w0 * u0.z; p3 += w0 * u0.w;
            q0 += w1 * u1.x; q1 += w1 * u1.y; q2 += w1 * u1.z; q3 += w1 * u1.w;
            p0 += w2 * u2.x; p1 += w2 * u2.y; p2 += w2 * u2.z; p3 += w2 * u2.w;
            q0 += w3 * u3.x; q1 += w3 * u3.y; q2 += w3 * u3.z; q3 += w3 * u3.w;
            h0 = n0; h1 = n1; h2 = n2; h3 = n3;
        }
        int rem = end - e;
        if (rem > 0) {
            float w0 = __int_as_float(h0.y);
            LOADU(u0, h0.x)
            p0 += w0 * u0.x; p1 += w0 * u0.y; p2 += w0 * u0.z; p3 += w0 * u0.w;
        }
        if (rem > 1) {
            float w1 = __int_as_float(h1.y);
            LOADU(u1, h1.x)
            q0 += w1 * u1.x; q1 += w1 * u1.y; q2 += w1 * u1.z; q3 += w1 * u1.w;
        }
        if (rem > 2) {
            float w2 = __int_as_float(h2.y);
            LOADU(u2, h2.x)
            p0 += w2 * u2.x; p1 += w2 * u2.y; p2 += w2 * u2.z; p3 += w2 * u2.w;
        }
#undef LOADU
        *(float4*)&zs[m * HH + lane * 4] =
            make_float4(p0 + q0, p1 + q1, p2 + q2, p3 + q3);
    }
    __syncwarp();   // warp-local: zs slice written by this warp only

    // ---- Phase B (per-warp): GEMM own zs slice [8,128] @ W[128,128] ----
    int tx = lane;
    ull acc[8][4];
#pragma unroll
    for (int i = 0; i < 8; i++)
#pragma unroll
        for (int j = 0; j < 4; j++) acc[i][j] = 0ull;

    const float* zrow = zs + (wrp * 8) * HH;
#pragma unroll 4
    for (int p = 0; p < 64; p++) {
        ull b0 = wp[p * HH + tx];
        ull b1 = wp[p * HH + tx + 32];
        ull b2 = wp[p * HH + tx + 64];
        ull b3 = wp[p * HH + tx + 96];
#pragma unroll
        for (int i = 0; i < 8; i++) {
            ull a2 = *(const ull*)&zrow[i * HH + 2 * p];
            acc[i][0] = ffma2(a2, b0, acc[i][0]);
            acc[i][1] = ffma2(a2, b1, acc[i][1]);
            acc[i][2] = ffma2(a2, b2, acc[i][2]);
            acc[i][3] = ffma2(a2, b3, acc[i][3]);
        }
    }
    float bs0 = bias[tx], bs1 = bias[tx + 32], bs2 = bias[tx + 64], bs3 = bias[tx + 96];
#pragma unroll
    for (int i = 0; i < 8; i++) {
        int r = row0 + wrp * 8 + i;
        if (r < NN) {
            float lo, hi;
            upk2(lo, hi, acc[i][0]); float o0 = lo + hi + bs0;
            upk2(lo, hi, acc[i][1]); float o1 = lo + hi + bs1;
            upk2(lo, hi, acc[i][2]); float o2 = lo + hi + bs2;
            upk2(lo, hi, acc[i][3]); float o3 = lo + hi + bs3;
            if (ACT == 1) { o0 = tanhf(o0); o1 = tanhf(o1); o2 = tanhf(o2); o3 = tanhf(o3); }
            if (OUTH) {
                __half* orow = (__half*)out + (size_t)r * HH + tx;
                orow[0]  = __float2half_rn(o0);
                orow[32] = __float2half_rn(o1);
                orow[64] = __float2half_rn(o2);
                orow[96] = __float2half_rn(o3);
            } else {
                float* orow = (float*)out + (size_t)r * HH + tx;
                orow[0] = o0; orow[32] = o1; orow[64] = o2; orow[96] = o3;
            }
        }
    }
}

// ---------------- standalone 128-col aggregation (xcat mesh cols, once) ----------
__global__ void k_agg128(const float* __restrict__ in, float* __restrict__ out,
                         int ostride, int ooff) {
    int i = blockIdx.x;
    int c = threadIdx.x;
    float di = g_dinv[i];
    float acc = di * di * in[(size_t)i * HH + c];
    int e = g_rowptr[i], end = g_rowptr[i + 1];
    for (; e + 2 <= end; e += 2) {
        int2 e0 = g_edge[e], e1 = g_edge[e + 1];
        acc += __int_as_float(e0.y) * in[(size_t)e0.x * HH + c];
        acc += __int_as_float(e1.y) * in[(size_t)e1.x * HH + c];
    }
    for (; e < end; e++) {
        int2 e0 = g_edge[e];
        acc += __int_as_float(e0.y) * in[(size_t)e0.x * HH + c];
    }
    out[(size_t)i * ostride + ooff + c] = acc;
}

// 8-column aggregate of meshfield -> g_small
__global__ void k_agg8(const float* __restrict__ in) {
    int i = blockIdx.x * blockDim.x + threadIdx.x;
    if (i >= NN) return;
    float di = g_dinv[i];
    const float4* inv = (const float4*)in;
    float4 u0 = inv[i * 2], u1 = inv[i * 2 + 1];
    float w = di * di;
    float a0 = w * u0.x, a1 = w * u0.y, a2 = w * u0.z, a3 = w * u0.w;
    float a4 = w * u1.x, a5 = w * u1.y, a6 = w * u1.z, a7 = w * u1.w;
    for (int e = g_rowptr[i]; e < g_rowptr[i + 1]; e++) {
        int2 ed = g_edge[e];
        float ww = __int_as_float(ed.y);
        float4 b0 = inv[ed.x * 2], b1 = inv[ed.x * 2 + 1];
        a0 += ww * b0.x; a1 += ww * b0.y; a2 += ww * b0.z; a3 += ww * b0.w;
        a4 += ww * b1.x; a5 += ww * b1.y; a6 += ww * b1.z; a7 += ww * b1.w;
    }
    float4* ov = (float4*)g_small;
    ov[i * 2]     = make_float4(a0, a1, a2, a3);
    ov[i * 2 + 1] = make_float4(a4, a5, a6, a7);
}

// 4-column aggregate of F_cur -> xcat columns [0,4)
__global__ void k_aggF() {
    int i = blockIdx.x * blockDim.x + threadIdx.x;
    if (i >= NN) return;
    float di = g_dinv[i];
    const float4* Fv = (const float4*)g_F;
    float4 f = Fv[i];
    float w = di * di;
    float a0 = w * f.x, a1 = w * f.y, a2 = w * f.z, a3 = w * f.w;
    for (int e = g_rowptr[i]; e < g_rowptr[i + 1]; e++) {
        int2 ed = g_edge[e];
        float ww = __int_as_float(ed.y);
        float4 u = Fv[ed.x];
        a0 += ww * u.x; a1 += ww * u.y; a2 += ww * u.z; a3 += ww * u.w;
    }
    *(float4*)(g_xcat + (size_t)i * KCAT) = make_float4(a0, a1, a2, a3);
}

// ---------------- generic GEMM: out[N,128] = x[N,K] @ W[K,128] + bias ----------
// Also zeroes g_stats (it is always followed by instance-norm stats).
__global__ void __launch_bounds__(256)
k_gemm128(const float* __restrict__ x, int K,
          const float* __restrict__ W, const float* __restrict__ bias,
          float* __restrict__ out) {
    __shared__ float xs[64 * KC];
    __shared__ float ws[KC * HH];
    int tid = threadIdx.x;
    if (blockIdx.x == 0) g_stats[tid] = 0.0f;   // 2*HH == 256
    int row0 = blockIdx.x * 64;
    int valid = NN - row0; if (valid > 64) valid = 64;
    int tx = tid & 31, ty = tid >> 5;

    ull acc01[8], acc23[8];
#pragma unroll
    for (int i = 0; i < 8; i++) { acc01[i] = 0ull; acc23[i] = 0ull; }

    for (int k0 = 0; k0 < K; k0 += KC) {
        int kc = K - k0; if (kc > KC) kc = KC;
        __syncthreads();
        {
            const float4* Wv = (const float4*)(W + (size_t)k0 * HH);
            float4* wv = (float4*)ws;
            for (int idx = tid; idx < kc * 32; idx += 256) wv[idx] = Wv[idx];
        }
        {
            const float* xg = x + (size_t)row0 * K + k0;
            for (int idx = tid; idx < valid * kc; idx += 256) {
                int r = idx / kc, j = idx - r * kc;
                xs[r * KC + j] = xg[(size_t)r * K + j];
            }
        }
        __syncthreads();
        const float* xsr = xs + (ty * 8) * KC;
        for (int j = 0; j < kc; j++) {
            float4 b = *(const float4*)&ws[j * HH + tx * 4];
            ull b01 = pk2(b.x, b.y), b23 = pk2(b.z, b.w);
#pragma unroll
            for (int i = 0; i < 8; i++) {
                float a = xsr[i * KC + j];
                ull ap = pk2(a, a);
                acc01[i] = ffma2(ap, b01, acc01[i]);
                acc23[i] = ffma2(ap, b23, acc23[i]);
            }
        }
    }
    float4 bv = *(const float4*)&bias[tx * 4];
#pragma unroll
    for (int i = 0; i < 8; i++) {
        int r = ty * 8 + i;
        if (row0 + r < NN) {
            float o0, o1, o2, o3;
            upk2(o0, o1, acc01[i]); upk2(o2, o3, acc23[i]);
            o0 += bv.x; o1 += bv.y; o2 += bv.z; o3 += bv.w;
            *(float4*)&out[(size_t)(row0 + r) * HH + tx * 4] = make_float4(o0, o1, o2, o3);
        }
    }
}

// small GEMM: g_h4[N,4] = x_half[N,128] @ W[128,4]
__global__ void k_gemm_to4(const __half* __restrict__ x, const float* __restrict__ W) {
    __shared__ float xs[32 * 129];
    __shared__ float ws[HH * 4];
    int tid = threadIdx.x;
    int row0 = blockIdx.x * 32;
    int valid = NN - row0; if (valid > 32) valid = 32;
    for (int idx = tid; idx < HH * 4; idx += 128) ws[idx] = W[idx];
    for (int idx = tid; idx < valid * HH; idx += 128) {
        int r = idx >> 7, k = idx & 127;
        xs[r * 129 + k] = __half2float(x[(size_t)row0 * HH + idx]);
    }
    __syncthreads();
    int r = tid >> 2, c = tid & 3;
    if (row0 + r < NN) {
        float acc = 0.0f;
#pragma unroll 8
        for (int k = 0; k < HH; k++) acc += xs[r * 129 + k] * ws[k * 4 + c];
        g_h4[(size_t)(row0 + r) * 4 + c] = acc;
    }
}

// ---------------- instance norm stats (per-channel over nodes) ----------------
__global__ void k_in_stats(const float* __restrict__ x) {
    int c = threadIdx.x;
    float s = 0.0f, q = 0.0f;
    for (int r = blockIdx.x; r < NN; r += gridDim.x) {
        float v = x[(size_t)r * HH + c];
        s += v; q += v * v;
    }
    atomicAdd(&g_stats[c], s);
    atomicAdd(&g_stats[HH + c], q);
}
__global__ void k_in_finalize() {
    int c = threadIdx.x;
    const float invn = 1.0f / (float)NN;
    float m = g_stats[c] * invn;
    float var = g_stats[HH + c] * invn - m * m;
    g_nm[c] = m;
    g_nr[c] = rsqrtf(var + EPSF);
}

// ---------------- recurrent step tail ----------------
__global__ void k_copyF0(const float* __restrict__ F0) {
    int i = blockIdx.x * blockDim.x + threadIdx.x;
    if (i < NN * NFF) g_F[i] = F0[i];
}
__global__ void k_step_final(const float* __restrict__ b9, float* __restrict__ out, int t) {
    int i = blockIdx.x * blockDim.x + threadIdx.x;
    if (i >= NN) return;
    float di = g_dinv[i];
    const float4* h4 = (const float4*)g_h4;
    float4 v = h4[i];
    float w = di * di;
    float a0 = b9[0] + w * v.x, a1 = b9[1] + w * v.y;
    float a2 = b9[2] + w * v.z, a3 = b9[3] + w * v.w;
    for (int e = g_rowptr[i]; e < g_rowptr[i + 1]; e++) {
        int2 ed = g_edge[e];
        float ww = __int_as_float(ed.y);
        float4 u = h4[ed.x];
        a0 += ww * u.x; a1 += ww * u.y; a2 += ww * u.z; a3 += ww * u.w;
    }
    float d0 = tanhf(a0), d1 = tanhf(a1), d2 = tanhf(a2), d3 = tanhf(a3);
    float4 f = ((float4*)g_F)[i];
    float n0 = tanhf(f.x + DTF * d0), n1 = tanhf(f.y + DTF * d1);
    float n2 = tanhf(f.z + DTF * d2), n3 = tanhf(f.w + DTF * d3);
    ((float4*)g_F)[i] = make_float4(n0, n1, n2, n3);
    int ob = i * TT * NFF + t * NFF;
    out[ob + 0] = n0; out[ob + 1] = n1; out[ob + 2] = n2; out[ob + 3] = n3;
    int ob2 = NN * TT * NFF + ob;
    out[ob2 + 0] = d0; out[ob2 + 1] = d1; out[ob2 + 2] = d2; out[ob2 + 3] = d3;
}

// fused-kernel variants
#define KF_NORM  k_fused<true,  true,  0, false, true>   // fp32 in (norm+relu) -> half out
#define KF_MID   k_fused<false, true,  0, true,  true>   // half in (relu)      -> half out
#define KF_TANH  k_fused<false, false, 1, true,  false>  // half in             -> fp32 tanh out

// ---------------- host orchestration ----------------
extern "C" void kernel_launch(void* const* d_in, const int* in_sizes, int n_in,
                              void* d_out, int out_size) {
    const float* F0        = (const float*)d_in[0];
    const int*   ei        = (const int*)d_in[1];
    const float* meshfield = (const float*)d_in[2];
    int w = (n_in >= 16 && in_sizes[3] == 1) ? 4 : 3;  // skip scalar n_time if present
    const float* mesh_W0 = (const float*)d_in[w + 0];
    const float* mesh_b0 = (const float*)d_in[w + 1];
    const float* mesh_Wh = (const float*)d_in[w + 2];
    const float* mesh_bh = (const float*)d_in[w + 3];
    const float* mesh_W9 = (const float*)d_in[w + 4];
    const float* mesh_b9 = (const float*)d_in[w + 5];
    const float* diff_W0 = (const float*)d_in[w + 6];
    const float* diff_b0 = (const float*)d_in[w + 7];
    const float* diff_Wh = (const float*)d_in[w + 8];
    const float* diff_bh = (const float*)d_in[w + 9];
    const float* diff_W9 = (const float*)d_in[w + 10];
    const float* diff_b9 = (const float*)d_in[w + 11];
    float* out = (float*)d_out;

    float *px, *pz, *pxcat, *psmall;
    __half *ph0, *ph1;
    cudaGetSymbolAddress((void**)&px, g_x);
    cudaGetSymbolAddress((void**)&pz, g_z);
    cudaGetSymbolAddress((void**)&pxcat, g_xcat);
    cudaGetSymbolAddress((void**)&psmall, g_small);
    cudaGetSymbolAddress((void**)&ph0, g_xh0);
    cudaGetSymbolAddress((void**)&ph1, g_xh1);

    cudaFuncSetAttribute(KF_NORM, cudaFuncAttributeMaxDynamicSharedMemorySize, FUSED_SMEM);
    cudaFuncSetAttribute(KF_MID,  cudaFuncAttributeMaxDynamicSharedMemorySize, FUSED_SMEM);
    cudaFuncSetAttribute(KF_TANH, cudaFuncAttributeMaxDynamicSharedMemorySize, FUSED_SMEM);

    const int GB = (NN + 63) / 64;
    const int FB = (NN + BM - 1) / BM;

    // --- graph normalization + CSR (weights precomputed) ---
    k_zero_cnt<<<(NN + 255) / 256, 256>>>();
    k_count<<<(EE + 255) / 256, 256>>>(ei);
    k_dinv<<<(NN + 255) / 256, 256>>>();
    k_scan<<<1, 1024>>>();
    k_fill<<<(EE + 255) / 256, 256>>>(ei);

    // --- mesh descriptor block ---
    k_agg8<<<(NN + 127) / 128, 128>>>(meshfield);                      // A@meshfield (8 cols)
    k_gemm128<<<GB, 256>>>(psmall, NMM, mesh_W0, mesh_b0, px);         // conv0 (+zero stats)
    k_in_stats<<<512, HH>>>(px);
    k_in_finalize<<<1, HH>>>();
    {
        KF_NORM<<<FB, 256, FUSED_SMEM>>>(px, mesh_Wh, mesh_bh, ph0);
        __half* cur = ph0; __half* nxt = ph1;
        for (int l = 1; l < DMID; l++) {
            KF_MID<<<FB, 256, FUSED_SMEM>>>(cur, mesh_Wh + (size_t)l * HH * HH,
                                            mesh_bh + (size_t)l * HH, nxt);
            __half* t2 = cur; cur = nxt; nxt = t2;
        }
        KF_TANH<<<FB, 256, FUSED_SMEM>>>(cur, mesh_W9, mesh_b9, pz);   // conv9+tanh (fp32)
        k_agg128<<<NN, HH>>>(pz, pxcat, KCAT, NFF);                    // xcat[:,4:132]
    }

    // --- recurrent differentiator ---
    k_copyF0<<<(NN * NFF + 255) / 256, 256>>>(F0);
    for (int t = 0; t < TT; t++) {
        k_aggF<<<(NN + 127) / 128, 128>>>();                           // xcat[:,0:4] = A@F
        k_gemm128<<<GB, 256>>>(pxcat, KCAT, diff_W0, diff_b0, px);     // conv0 (+zero stats)
        k_in_stats<<<512, HH>>>(px);
        k_in_finalize<<<1, HH>>>();
        KF_NORM<<<FB, 256, FUSED_SMEM>>>(px, diff_Wh, diff_bh, ph0);
        __half* cur = ph0; __half* nxt = ph1;
        for (int l = 1; l < DMID; l++) {
            KF_MID<<<FB, 256, FUSED_SMEM>>>(cur, diff_Wh + (size_t)l * HH * HH,
                                            diff_bh + (size_t)l * HH, nxt);
            __half* t2 = cur; cur = nxt; nxt = t2;
        }
        k_gemm_to4<<<(NN + 31) / 32, 128>>>(cur, diff_W9);             // half x @ W9 -> h4
        k_step_final<<<(NN + 127) / 128, 128>>>(diff_b9, out, t);      // A@h4+b9, Euler, write
    }
    (void)out_size;
}

// round 8
// speedup vs baseline: 1.5368x; 1.5368x over previous
#include <cuda_runtime.h>
#include <cuda_fp16.h>
#include <math.h>

#define NN   30000
#define EE   480000
#define HH   128
#define NFF  4
#define NMM  8
#define TT   4
#define DMID 8
#define KCAT 132
#define KC   64
#define BM   64          // fused tile: nodes per block
#define RS   136         // smem row stride in halves (128 + 8 pad, 272 B)
#define EPSF 1e-5f
#define DTF  0.1f

#define WS_BYTES (HH * RS * 2)                  // 34816: W fp16 [128][136]
#define ZS_BYTES (BM * RS * 2)                  // 17408: zs fp16 [64][136]
#define FUSED_SMEM (WS_BYTES + ZS_BYTES)        // 52224

typedef unsigned long long ull;
typedef unsigned int u32;

// ---------------- scratch (static device memory; no allocations) ----------------
__device__ int    g_cnt[NN];
__device__ float  g_dinv[NN];
__device__ int    g_rowptr[NN + 1];
__device__ int    g_cursor[NN];
__device__ int2   g_edge[EE + 8];      // {src, bits(dinv[src]*dinv[dst])}; +8 pad
__device__ float  g_x[NN * HH];
__device__ float  g_z[NN * HH];
__device__ __half g_xh0[NN * HH];      // half activation ping
__device__ __half g_xh1[NN * HH];      // half activation pong
__device__ float  g_xcat[NN * KCAT];   // [aggF(4) | agg_mesh(128)]
__device__ float  g_small[NN * NMM];   // aggregated meshfield (8 cols)
__device__ float  g_F[NN * NFF];
__device__ float  g_h4[NN * NFF];
__device__ float  g_stats[2 * HH];
__device__ float  g_nm[HH];            // per-channel mean
__device__ float  g_nr[HH];            // per-channel rstd

// ---------------- packed fp32 helpers (for the K!=128 fp32 GEMM) ----------------
__device__ __forceinline__ ull pk2(float lo, float hi) {
    ull o; asm("mov.b64 %0, {%1, %2};" : "=l"(o) : "f"(lo), "f"(hi)); return o;
}
__device__ __forceinline__ void upk2(float& lo, float& hi, ull v) {
    asm("mov.b64 {%0, %1}, %2;" : "=f"(lo), "=f"(hi) : "l"(v));
}
__device__ __forceinline__ ull ffma2(ull a, ull b, ull c) {
    ull d; asm("fma.rn.f32x2 %0, %1, %2, %3;" : "=l"(d) : "l"(a), "l"(b), "l"(c)); return d;
}

// ---------------- mma helpers ----------------
__device__ __forceinline__ void ldsm_x4(u32& a0, u32& a1, u32& a2, u32& a3, u32 addr) {
    asm volatile("ldmatrix.sync.aligned.m8n8.x4.shared.b16 {%0,%1,%2,%3}, [%4];"
                 : "=r"(a0), "=r"(a1), "=r"(a2), "=r"(a3) : "r"(addr));
}
__device__ __forceinline__ void ldsm_x2t(u32& b0, u32& b1, u32 addr) {
    asm volatile("ldmatrix.sync.aligned.m8n8.x2.trans.shared.b16 {%0,%1}, [%2];"
                 : "=r"(b0), "=r"(b1) : "r"(addr));
}
__device__ __forceinline__ void mma16816(float& d0, float& d1, float& d2, float& d3,
                                         u32 a0, u32 a1, u32 a2, u32 a3, u32 b0, u32 b1) {
    asm volatile("mma.sync.aligned.m16n8k16.row.col.f32.f16.f16.f32 "
                 "{%0,%1,%2,%3}, {%4,%5,%6,%7}, {%8,%9}, {%0,%1,%2,%3};"
                 : "+f"(d0), "+f"(d1), "+f"(d2), "+f"(d3)
                 : "r"(a0), "r"(a1), "r"(a2), "r"(a3), "r"(b0), "r"(b1));
}

// row loader: fp32 (512B rows) or fp16 (256B rows), returns this lane's 4 cols
template <bool INH>
__device__ __forceinline__ float4 ldrow(const void* in, int s, int lane) {
    if (INH) {
        uint2 u = ((const uint2*)in)[(size_t)s * 32 + lane];
        float2 a = __half22float2(*(const __half2*)&u.x);
        float2 b = __half22float2(*(const __half2*)&u.y);
        return make_float4(a.x, a.y, b.x, b.y);
    } else {
        return ((const float4*)in)[(size_t)s * 32 + lane];
    }
}

// ---------------- graph normalization + CSR build ----------------
__global__ void k_zero_cnt() {
    int i = blockIdx.x * blockDim.x + threadIdx.x;
    if (i < NN) g_cnt[i] = 0;
    if (i < 8) g_edge[EE + i] = make_int2(0, 0);
}
__global__ void k_count(const int* __restrict__ ei) {
    int e = blockIdx.x * blockDim.x + threadIdx.x;
    if (e < EE) atomicAdd(&g_cnt[ei[EE + e]], 1);
}
__global__ void k_dinv() {
    int i = blockIdx.x * blockDim.x + threadIdx.x;
    if (i < NN) g_dinv[i] = rsqrtf((float)g_cnt[i] + 1.0f);  // deg includes self loop
}
__global__ void k_scan() {
    __shared__ int partial[1024];
    const int CH = (NN + 1023) / 1024;
    int tid = threadIdx.x;
    int base = tid * CH;
    int s = 0;
    for (int j = 0; j < CH; j++) {
        int idx = base + j;
        if (idx < NN) s += g_cnt[idx];
    }
    partial[tid] = s;
    __syncthreads();
    for (int off = 1; off < 1024; off <<= 1) {
        int v = (tid >= off) ? partial[tid - off] : 0;
        __syncthreads();
        partial[tid] += v;
        __syncthreads();
    }
    int run = partial[tid] - s;  // exclusive prefix
    for (int j = 0; j < CH; j++) {
        int idx = base + j;
        if (idx < NN) {
            g_rowptr[idx] = run;
            g_cursor[idx] = run;
            run += g_cnt[idx];
        }
    }
    if (tid == 1023) g_rowptr[NN] = partial[1023];
}
__global__ void k_fill(const int* __restrict__ ei) {
    int e = blockIdx.x * blockDim.x + threadIdx.x;
    if (e < EE) {
        int s = ei[e];
        int d = ei[EE + e];
        int p = atomicAdd(&g_cursor[d], 1);
        g_edge[p] = make_int2(s, __float_as_int(g_dinv[s] * g_dinv[d]));
    }
}

// ---------------- FUSED [norm] -> agg(+relu) -> tensor-core GEMM ----------------
// smem: ws = W as fp16 [128][136], zs = gathered rows fp16 [64][136].
// Phase A: 8 warps gather 64 rows (fp32 accum), write fp16 to zs.
// Phase B: warp w computes m-tile (w%4)*16, n-half (w/4)*64 via mma.m16n8k16.
template <bool NORM, bool RELU, int ACT, bool INH, bool OUTH>
__global__ void __launch_bounds__(256)
k_fused(const void* __restrict__ in, const float* __restrict__ W,
        const float* __restrict__ bias, void* __restrict__ out) {
    extern __shared__ char smem[];
    __half* ws = (__half*)smem;
    __half* zs = (__half*)(smem + WS_BYTES);

    int tid = threadIdx.x;
    int lane = tid & 31, wrp = tid >> 5;
    int row0 = blockIdx.x * BM;
    const int2* ge = g_edge;

    // ---- stage W (fp32 -> fp16), coalesced float4 loads ----
    for (int idx4 = tid; idx4 < HH * HH / 4; idx4 += 256) {
        int k = idx4 >> 5, n4 = (idx4 & 31) * 4;
        float4 v = *(const float4*)&W[(size_t)k * HH + n4];
        __half2* dst = (__half2*)&ws[k * RS + n4];
        dst[0] = __floats2half2_rn(v.x, v.y);
        dst[1] = __floats2half2_rn(v.z, v.w);
    }

    float4 m4, r4;
    if (NORM) {
        m4 = ((const float4*)g_nm)[lane];
        r4 = ((const float4*)g_nr)[lane];
    }

    // ---- Phase A (per-warp): gather 8 rows into zs ----
    for (int mi = 0; mi < 8; mi++) {
        int m = wrp * 8 + mi;
        int i = row0 + m;
        if (i >= NN) break;
        float di = g_dinv[i];

#define LOADU(u, s)                                                        \
        float4 u = ldrow<INH>(in, (s), lane);                              \
        if (NORM) { u.x = (u.x - m4.x) * r4.x; u.y = (u.y - m4.y) * r4.y;  \
                    u.z = (u.z - m4.z) * r4.z; u.w = (u.w - m4.w) * r4.w; }\
        if (RELU) { u.x = fmaxf(u.x, 0.f); u.y = fmaxf(u.y, 0.f);          \
                    u.z = fmaxf(u.z, 0.f); u.w = fmaxf(u.w, 0.f); }

        LOADU(vs, i)
        float w = di * di;
        float p0 = w * vs.x, p1 = w * vs.y, p2 = w * vs.z, p3 = w * vs.w;
        float q0 = 0.f, q1 = 0.f, q2 = 0.f, q3 = 0.f;
        int e = g_rowptr[i], end = g_rowptr[i + 1];
        int2 h0 = ge[e], h1 = ge[e + 1], h2 = ge[e + 2], h3 = ge[e + 3];
        for (; e + 4 <= end; e += 4) {
            int2 n0 = ge[e + 4], n1 = ge[e + 5], n2 = ge[e + 6], n3 = ge[e + 7];
            float w0 = __int_as_float(h0.y), w1 = __int_as_float(h1.y);
            float w2 = __int_as_float(h2.y), w3 = __int_as_float(h3.y);
            LOADU(u0, h0.x) LOADU(u1, h1.x) LOADU(u2, h2.x) LOADU(u3, h3.x)
            p0 += w0 * u0.x; p1 += w0 * u0.y; p2 += w0 * u0.z; p3 += w0 * u0.w;
            q0 += w1 * u1.x; q1 += w1 * u1.y; q2 += w1 * u1.z; q3 += w1 * u1.w;
            p0 += w2 * u2.x; p1 += w2 * u2.y; p2 += w2 * u2.z; p3 += w2 * u2.w;
            q0 += w3 * u3.x; q1 += w3 * u3.y; q2 += w3 * u3.z; q3 += w3 * u3.w;
            h0 = n0; h1 = n1; h2 = n2; h3 = n3;
        }
        int rem = end - e;
        if (rem > 0) {
            float w0 = __int_as_float(h0.y);
            LOADU(u0, h0.x)
            p0 += w0 * u0.x; p1 += w0 * u0.y; p2 += w0 * u0.z; p3 += w0 * u0.w;
        }
        if (rem > 1) {
            float w1 = __int_as_float(h1.y);
            LOADU(u1, h1.x)
            q0 += w1 * u1.x; q1 += w1 * u1.y; q2 += w1 * u1.z; q3 += w1 * u1.w;
        }
        if (rem > 2) {
            float w2 = __int_as_float(h2.y);
            LOADU(u2, h2.x)
            p0 += w2 * u2.x; p1 += w2 * u2.y; p2 += w2 * u2.z; p3 += w2 * u2.w;
        }
#undef LOADU
        __half2* zrow = (__half2*)&zs[m * RS + lane * 4];
        zrow[0] = __floats2half2_rn(p0 + q0, p1 + q1);
        zrow[1] = __floats2half2_rn(p2 + q2, p3 + q3);
    }
    __syncthreads();   // ws + zs ready

    // ---- Phase B: warp (wrp%4) m-tile, (wrp/4) n-half; mma.m16n8k16 ----
    int m0 = (wrp & 3) * 16;
    int n0b = (wrp >> 2) * 64;
    u32 zsu = (u32)__cvta_generic_to_shared(zs);
    u32 wsu = (u32)__cvta_generic_to_shared(ws);

    float acc[8][4];
#pragma unroll
    for (int nt = 0; nt < 8; nt++)
#pragma unroll
        for (int j = 0; j < 4; j++) acc[nt][j] = 0.0f;

    // A-frag lane address: row = m0 + (lane&15), col-half = (lane>>4)*8
    u32 aaddr = zsu + (u32)((m0 + (lane & 15)) * (RS * 2)) + (u32)((lane >> 4) * 16);
    // B-frag lane address: k-row = k0 + (lane&15), col = n0
    u32 baddr0 = wsu + (u32)((lane & 15) * (RS * 2));

#pragma unroll
    for (int kk = 0; kk < 8; kk++) {
        u32 a0, a1, a2, a3;
        ldsm_x4(a0, a1, a2, a3, aaddr + kk * 32);            // k0 = 16*kk -> 32 B
#pragma unroll
        for (int nt = 0; nt < 8; nt++) {
            u32 b0, b1;
            ldsm_x2t(b0, b1, baddr0 + kk * 16 * (RS * 2) + (n0b + nt * 8) * 2);
            mma16816(acc[nt][0], acc[nt][1], acc[nt][2], acc[nt][3],
                     a0, a1, a2, a3, b0, b1);
        }
    }

    // ---- epilogue: bias (+tanh), store ----
    int qr = lane >> 2;           // 0..7
    int qc = (lane & 3) * 2;      // 0,2,4,6
    int r0 = row0 + m0 + qr;
#pragma unroll
    for (int nt = 0; nt < 8; nt++) {
        int c = n0b + nt * 8 + qc;
        float2 bv = *(const float2*)&bias[c];
        float o0 = acc[nt][0] + bv.x, o1 = acc[nt][1] + bv.y;
        float o2 = acc[nt][2] + bv.x, o3 = acc[nt][3] + bv.y;
        if (ACT == 1) { o0 = tanhf(o0); o1 = tanhf(o1); o2 = tanhf(o2); o3 = tanhf(o3); }
        if (OUTH) {
            if (r0 < NN)
                *(__half2*)((__half*)out + (size_t)r0 * HH + c) = __floats2half2_rn(o0, o1);
            if (r0 + 8 < NN)
                *(__half2*)((__half*)out + (size_t)(r0 + 8) * HH + c) = __floats2half2_rn(o2, o3);
        } else {
            if (r0 < NN)
                *(float2*)((float*)out + (size_t)r0 * HH + c) = make_float2(o0, o1);
            if (r0 + 8 < NN)
                *(float2*)((float*)out + (size_t)(r0 + 8) * HH + c) = make_float2(o2, o3);
        }
    }
}

// ---------------- standalone 128-col aggregation (xcat mesh cols, once) ----------
__global__ void k_agg128(const float* __restrict__ in, float* __restrict__ out,
                         int ostride, int ooff) {
    int i = blockIdx.x;
    int c = threadIdx.x;
    float di = g_dinv[i];
    float acc = di * di * in[(size_t)i * HH + c];
    int e = g_rowptr[i], end = g_rowptr[i + 1];
    for (; e + 2 <= end; e += 2) {
        int2 e0 = g_edge[e], e1 = g_edge[e + 1];
        acc += __int_as_float(e0.y) * in[(size_t)e0.x * HH + c];
        acc += __int_as_float(e1.y) * in[(size_t)e1.x * HH + c];
    }
    for (; e < end; e++) {
        int2 e0 = g_edge[e];
        acc += __int_as_float(e0.y) * in[(size_t)e0.x * HH + c];
    }
    out[(size_t)i * ostride + ooff + c] = acc;
}

// 8-column aggregate of meshfield -> g_small
__global__ void k_agg8(const float* __restrict__ in) {
    int i = blockIdx.x * blockDim.x + threadIdx.x;
    if (i >= NN) return;
    float di = g_dinv[i];
    const float4* inv = (const float4*)in;
    float4 u0 = inv[i * 2], u1 = inv[i * 2 + 1];
    float w = di * di;
    float a0 = w * u0.x, a1 = w * u0.y, a2 = w * u0.z, a3 = w * u0.w;
    float a4 = w * u1.x, a5 = w * u1.y, a6 = w * u1.z, a7 = w * u1.w;
    for (int e = g_rowptr[i]; e < g_rowptr[i + 1]; e++) {
        int2 ed = g_edge[e];
        float ww = __int_as_float(ed.y);
        float4 b0 = inv[ed.x * 2], b1 = inv[ed.x * 2 + 1];
        a0 += ww * b0.x; a1 += ww * b0.y; a2 += ww * b0.z; a3 += ww * b0.w;
        a4 += ww * b1.x; a5 += ww * b1.y; a6 += ww * b1.z; a7 += ww * b1.w;
    }
    float4* ov = (float4*)g_small;
    ov[i * 2]     = make_float4(a0, a1, a2, a3);
    ov[i * 2 + 1] = make_float4(a4, a5, a6, a7);
}

// 4-column aggregate of F_cur -> xcat columns [0,4)
__global__ void k_aggF() {
    int i = blockIdx.x * blockDim.x + threadIdx.x;
    if (i >= NN) return;
    float di = g_dinv[i];
    const float4* Fv = (const float4*)g_F;
    float4 f = Fv[i];
    float w = di * di;
    float a0 = w * f.x, a1 = w * f.y, a2 = w * f.z, a3 = w * f.w;
    for (int e = g_rowptr[i]; e < g_rowptr[i + 1]; e++) {
        int2 ed = g_edge[e];
        float ww = __int_as_float(ed.y);
        float4 u = Fv[ed.x];
        a0 += ww * u.x; a1 += ww * u.y; a2 += ww * u.z; a3 += ww * u.w;
    }
    *(float4*)(g_xcat + (size_t)i * KCAT) = make_float4(a0, a1, a2, a3);
}

// ---------------- generic fp32 GEMM: out[N,128] = x[N,K] @ W[K,128] + bias -------
// Also zeroes g_stats (it is always followed by instance-norm stats).
__global__ void __launch_bounds__(256)
k_gemm128(const float* __restrict__ x, int K,
          const float* __restrict__ W, const float* __restrict__ bias,
          float* __restrict__ out) {
    __shared__ float xs[64 * KC];
    __shared__ float wsf[KC * HH];
    int tid = threadIdx.x;
    if (blockIdx.x == 0) g_stats[tid] = 0.0f;   // 2*HH == 256
    int row0 = blockIdx.x * 64;
    int valid = NN - row0; if (valid > 64) valid = 64;
    int tx = tid & 31, ty = tid >> 5;

    ull acc01[8], acc23[8];
#pragma unroll
    for (int i = 0; i < 8; i++) { acc01[i] = 0ull; acc23[i] = 0ull; }

    for (int k0 = 0; k0 < K; k0 += KC) {
        int kc = K - k0; if (kc > KC) kc = KC;
        __syncthreads();
        {
            const float4* Wv = (const float4*)(W + (size_t)k0 * HH);
            float4* wv = (float4*)wsf;
            for (int idx = tid; idx < kc * 32; idx += 256) wv[idx] = Wv[idx];
        }
        {
            const float* xg = x + (size_t)row0 * K + k0;
            for (int idx = tid; idx < valid * kc; idx += 256) {
                int r = idx / kc, j = idx - r * kc;
                xs[r * KC + j] = xg[(size_t)r * K + j];
            }
        }
        __syncthreads();
        const float* xsr = xs + (ty * 8) * KC;
        for (int j = 0; j < kc; j++) {
            float4 b = *(const float4*)&wsf[j * HH + tx * 4];
            ull b01 = pk2(b.x, b.y), b23 = pk2(b.z, b.w);
#pragma unroll
            for (int i = 0; i < 8; i++) {
                float a = xsr[i * KC + j];
                ull ap = pk2(a, a);
                acc01[i] = ffma2(ap, b01, acc01[i]);
                acc23[i] = ffma2(ap, b23, acc23[i]);
            }
        }
    }
    float4 bv = *(const float4*)&bias[tx * 4];
#pragma unroll
    for (int i = 0; i < 8; i++) {
        int r = ty * 8 + i;
        if (row0 + r < NN) {
            float o0, o1, o2, o3;
            upk2(o0, o1, acc01[i]); upk2(o2, o3, acc23[i]);
            o0 += bv.x; o1 += bv.y; o2 += bv.z; o3 += bv.w;
            *(float4*)&out[(size_t)(row0 + r) * HH + tx * 4] = make_float4(o0, o1, o2, o3);
        }
    }
}

// small GEMM: g_h4[N,4] = x_half[N,128] @ W[128,4]
__global__ void k_gemm_to4(const __half* __restrict__ x, const float* __restrict__ W) {
    __shared__ float xs[32 * 129];
    __shared__ float wsf[HH * 4];
    int tid = threadIdx.x;
    int row0 = blockIdx.x * 32;
    int valid = NN - row0; if (valid > 32) valid = 32;
    for (int idx = tid; idx < HH * 4; idx += 128) wsf[idx] = W[idx];
    for (int idx = tid; idx < valid * HH; idx += 128) {
        int r = idx >> 7, k = idx & 127;
        xs[r * 129 + k] = __half2float(x[(size_t)row0 * HH + idx]);
    }
    __syncthreads();
    int r = tid >> 2, c = tid & 3;
    if (row0 + r < NN) {
        float acc = 0.0f;
#pragma unroll 8
        for (int k = 0; k < HH; k++) acc += xs[r * 129 + k] * wsf[k * 4 + c];
        g_h4[(size_t)(row0 + r) * 4 + c] = acc;
    }
}

// ---------------- instance norm stats (per-channel over nodes) ----------------
__global__ void k_in_stats(const float* __restrict__ x) {
    int c = threadIdx.x;
    float s = 0.0f, q = 0.0f;
    for (int r = blockIdx.x; r < NN; r += gridDim.x) {
        float v = x[(size_t)r * HH + c];
        s += v; q += v * v;
    }
    atomicAdd(&g_stats[c], s);
    atomicAdd(&g_stats[HH + c], q);
}
__global__ void k_in_finalize() {
    int c = threadIdx.x;
    const float invn = 1.0f / (float)NN;
    float m = g_stats[c] * invn;
    float var = g_stats[HH + c] * invn - m * m;
    g_nm[c] = m;
    g_nr[c] = rsqrtf(var + EPSF);
}

// ---------------- recurrent step tail ----------------
__global__ void k_copyF0(const float* __restrict__ F0) {
    int i = blockIdx.x * blockDim.x + threadIdx.x;
    if (i < NN * NFF) g_F[i] = F0[i];
}
__global__ void k_step_final(const float* __restrict__ b9, float* __restrict__ out, int t) {
    int i = blockIdx.x * blockDim.x + threadIdx.x;
    if (i >= NN) return;
    float di = g_dinv[i];
    const float4* h4 = (const float4*)g_h4;
    float4 v = h4[i];
    float w = di * di;
    float a0 = b9[0] + w * v.x, a1 = b9[1] + w * v.y;
    float a2 = b9[2] + w * v.z, a3 = b9[3] + w * v.w;
    for (int e = g_rowptr[i]; e < g_rowptr[i + 1]; e++) {
        int2 ed = g_edge[e];
        float ww = __int_as_float(ed.y);
        float4 u = h4[ed.x];
        a0 += ww * u.x; a1 += ww * u.y; a2 += ww * u.z; a3 += ww * u.w;
    }
    float d0 = tanhf(a0), d1 = tanhf(a1), d2 = tanhf(a2), d3 = tanhf(a3);
    float4 f = ((float4*)g_F)[i];
    float n0 = tanhf(f.x + DTF * d0), n1 = tanhf(f.y + DTF * d1);
    float n2 = tanhf(f.z + DTF * d2), n3 = tanhf(f.w + DTF * d3);
    ((float4*)g_F)[i] = make_float4(n0, n1, n2, n3);
    int ob = i * TT * NFF + t * NFF;
    out[ob + 0] = n0; out[ob + 1] = n1; out[ob + 2] = n2; out[ob + 3] = n3;
    int ob2 = NN * TT * NFF + ob;
    out[ob2 + 0] = d0; out[ob2 + 1] = d1; out[ob2 + 2] = d2; out[ob2 + 3] = d3;
}

// fused-kernel variants
#define KF_NORM  k_fused<true,  true,  0, false, true>   // fp32 in (norm+relu) -> half out
#define KF_MID   k_fused<false, true,  0, true,  true>   // half in (relu)      -> half out
#define KF_TANH  k_fused<false, false, 1, true,  false>  // half in             -> fp32 tanh out

// ---------------- host orchestration ----------------
extern "C" void kernel_launch(void* const* d_in, const int* in_sizes, int n_in,
                              void* d_out, int out_size) {
    const float* F0        = (const float*)d_in[0];
    const int*   ei        = (const int*)d_in[1];
    const float* meshfield = (const float*)d_in[2];
    int w = (n_in >= 16 && in_sizes[3] == 1) ? 4 : 3;  // skip scalar n_time if present
    const float* mesh_W0 = (const float*)d_in[w + 0];
    const float* mesh_b0 = (const float*)d_in[w + 1];
    const float* mesh_Wh = (const float*)d_in[w + 2];
    const float* mesh_bh = (const float*)d_in[w + 3];
    const float* mesh_W9 = (const float*)d_in[w + 4];
    const float* mesh_b9 = (const float*)d_in[w + 5];
    const float* diff_W0 = (const float*)d_in[w + 6];
    const float* diff_b0 = (const float*)d_in[w + 7];
    const float* diff_Wh = (const float*)d_in[w + 8];
    const float* diff_bh = (const float*)d_in[w + 9];
    const float* diff_W9 = (const float*)d_in[w + 10];
    const float* diff_b9 = (const float*)d_in[w + 11];
    float* out = (float*)d_out;

    float *px, *pz, *pxcat, *psmall;
    __half *ph0, *ph1;
    cudaGetSymbolAddress((void**)&px, g_x);
    cudaGetSymbolAddress((void**)&pz, g_z);
    cudaGetSymbolAddress((void**)&pxcat, g_xcat);
    cudaGetSymbolAddress((void**)&psmall, g_small);
    cudaGetSymbolAddress((void**)&ph0, g_xh0);
    cudaGetSymbolAddress((void**)&ph1, g_xh1);

    cudaFuncSetAttribute(KF_NORM, cudaFuncAttributeMaxDynamicSharedMemorySize, FUSED_SMEM);
    cudaFuncSetAttribute(KF_MID,  cudaFuncAttributeMaxDynamicSharedMemorySize, FUSED_SMEM);
    cudaFuncSetAttribute(KF_TANH, cudaFuncAttributeMaxDynamicSharedMemorySize, FUSED_SMEM);

    const int GB = (NN + 63) / 64;
    const int FB = (NN + BM - 1) / BM;

    // --- graph normalization + CSR (weights precomputed) ---
    k_zero_cnt<<<(NN + 255) / 256, 256>>>();
    k_count<<<(EE + 255) / 256, 256>>>(ei);
    k_dinv<<<(NN + 255) / 256, 256>>>();
    k_scan<<<1, 1024>>>();
    k_fill<<<(EE + 255) / 256, 256>>>(ei);

    // --- mesh descriptor block ---
    k_agg8<<<(NN + 127) / 128, 128>>>(meshfield);                      // A@meshfield (8 cols)
    k_gemm128<<<GB, 256>>>(psmall, NMM, mesh_W0, mesh_b0, px);         // conv0 (+zero stats)
    k_in_stats<<<512, HH>>>(px);
    k_in_finalize<<<1, HH>>>();
    {
        KF_NORM<<<FB, 256, FUSED_SMEM>>>(px, mesh_Wh, mesh_bh, ph0);
        __half* cur = ph0; __half* nxt = ph1;
        for (int l = 1; l < DMID; l++) {
            KF_MID<<<FB, 256, FUSED_SMEM>>>(cur, mesh_Wh + (size_t)l * HH * HH,
                                            mesh_bh + (size_t)l * HH, nxt);
            __half* t2 = cur; cur = nxt; nxt = t2;
        }
        KF_TANH<<<FB, 256, FUSED_SMEM>>>(cur, mesh_W9, mesh_b9, pz);   // conv9+tanh (fp32)
        k_agg128<<<NN, HH>>>(pz, pxcat, KCAT, NFF);                    // xcat[:,4:132]
    }

    // --- recurrent differentiator ---
    k_copyF0<<<(NN * NFF + 255) / 256, 256>>>(F0);
    for (int t = 0; t < TT; t++) {
        k_aggF<<<(NN + 127) / 128, 128>>>();                           // xcat[:,0:4] = A@F
        k_gemm128<<<GB, 256>>>(pxcat, KCAT, diff_W0, diff_b0, px);     // conv0 (+zero stats)
        k_in_stats<<<512, HH>>>(px);
        k_in_finalize<<<1, HH>>>();
        KF_NORM<<<FB, 256, FUSED_SMEM>>>(px, diff_Wh, diff_bh, ph0);
        __half* cur = ph0; __half* nxt = ph1;
        for (int l = 1; l < DMID; l++) {
            KF_MID<<<FB, 256, FUSED_SMEM>>>(cur, diff_Wh + (size_t)l * HH * HH,
                                            diff_bh + (size_t)l * HH, nxt);
            __half* t2 = cur; cur = nxt; nxt = t2;
        }
        k_gemm_to4<<<(NN + 31) / 32, 128>>>(cur, diff_W9);             // half x @ W9 -> h4
        k_step_final<<<(NN + 127) / 128, 128>>>(diff_b9, out, t);      // A@h4+b9, Euler, write
    }
    (void)out_size;
}

// round 12
// speedup vs baseline: 1.6599x; 1.0801x over previous
#include <cuda_runtime.h>
#include <cuda_fp16.h>
#include <math.h>

#define NN   30000
#define EE   480000
#define HH   128
#define NFF  4
#define NMM  8
#define TT   4
#define DMID 8
#define KCAT 132
#define KC   64
#define BM   64          // fused tile: nodes per block
#define RS   136         // smem row stride in halves (128 + 8 pad, 272 B)
#define RS2  152         // conv0 x-tile row stride in halves (144 + 8 pad, 304 B)
#define EPSF 1e-5f
#define DTF  0.1f

#define WS_BYTES (HH * RS * 2)                  // 34816: W fp16 [128][136]
#define ZS_BYTES (BM * RS * 2)                  // 17408: zs fp16 [64][136]
#define FUSED_SMEM (WS_BYTES + ZS_BYTES)        // 52224

#define C0_WS (144 * RS * 2)                    // 39168: W0 fp16 [144][136] (K-padded)
#define C0_XS (BM * RS2 * 2)                    // 19456: x fp16 [64][152]
#define CONV0_SMEM (C0_WS + C0_XS)              // 58624

#define SCAN_SMEM ((NN + 1024) * 4)             // 124096

typedef unsigned long long ull;
typedef unsigned int u32;

// ---------------- scratch (static device memory; no allocations) ----------------
__device__ int    g_cnt[NN];
__device__ float  g_dinv[NN];
__device__ int    g_rowptr[NN + 1];
__device__ int    g_cursor[NN];
__device__ int2   g_edge[EE + 8];      // {src, bits(dinv[src]*dinv[dst])}; +8 pad
__device__ float  g_x[NN * HH];
__device__ float  g_z[NN * HH];
__device__ __half g_xh0[NN * HH];      // half activation ping
__device__ __half g_xh1[NN * HH];      // half activation pong
__device__ float  g_xcat[NN * KCAT];   // aggmesh [N,128] fp32 (stride 128, time-invariant)
__device__ float  g_small[NN * NMM];   // aggregated meshfield (8 cols)
__device__ float  g_F[NN * NFF];
__device__ float  g_h4[NN * NFF];
__device__ float  g_stats[2 * HH];

// ---------------- packed fp32 helpers (for the K=8 fp32 GEMM) ----------------
__device__ __forceinline__ ull pk2(float lo, float hi) {
    ull o; asm("mov.b64 %0, {%1, %2};" : "=l"(o) : "f"(lo), "f"(hi)); return o;
}
__device__ __forceinline__ void upk2(float& lo, float& hi, ull v) {
    asm("mov.b64 {%0, %1}, %2;" : "=f"(lo), "=f"(hi) : "l"(v));
}
__device__ __forceinline__ ull ffma2(ull a, ull b, ull c) {
    ull d; asm("fma.rn.f32x2 %0, %1, %2, %3;" : "=l"(d) : "l"(a), "l"(b), "l"(c)); return d;
}

// ---------------- mma helpers ----------------
__device__ __forceinline__ void ldsm_x4(u32& a0, u32& a1, u32& a2, u32& a3, u32 addr) {
    asm volatile("ldmatrix.sync.aligned.m8n8.x4.shared.b16 {%0,%1,%2,%3}, [%4];"
                 : "=r"(a0), "=r"(a1), "=r"(a2), "=r"(a3) : "r"(addr));
}
__device__ __forceinline__ void ldsm_x2t(u32& b0, u32& b1, u32 addr) {
    asm volatile("ldmatrix.sync.aligned.m8n8.x2.trans.shared.b16 {%0,%1}, [%2];"
                 : "=r"(b0), "=r"(b1) : "r"(addr));
}
__device__ __forceinline__ void mma16816(float& d0, float& d1, float& d2, float& d3,
                                         u32 a0, u32 a1, u32 a2, u32 a3, u32 b0, u32 b1) {
    asm volatile("mma.sync.aligned.m16n8k16.row.col.f32.f16.f16.f32 "
                 "{%0,%1,%2,%3}, {%4,%5,%6,%7}, {%8,%9}, {%0,%1,%2,%3};"
                 : "+f"(d0), "+f"(d1), "+f"(d2), "+f"(d3)
                 : "r"(a0), "r"(a1), "r"(a2), "r"(a3), "r"(b0), "r"(b1));
}

// row loader: fp32 (512B rows) or fp16 (256B rows), returns this lane's 4 cols
template <bool INH>
__device__ __forceinline__ float4 ldrow(const void* in, int s, int lane) {
    if (INH) {
        uint2 u = ((const uint2*)in)[(size_t)s * 32 + lane];
        float2 a = __half22float2(*(const __half2*)&u.x);
        float2 b = __half22float2(*(const __half2*)&u.y);
        return make_float4(a.x, a.y, b.x, b.y);
    } else {
        return ((const float4*)in)[(size_t)s * 32 + lane];
    }
}

// ---------------- graph normalization + CSR build ----------------
__global__ void k_zero_cnt() {
    int i = blockIdx.x * blockDim.x + threadIdx.x;
    if (i < NN) g_cnt[i] = 0;
    if (i < 8) g_edge[EE + i] = make_int2(0, 0);
}
__global__ void k_count(const int* __restrict__ ei) {
    int e = blockIdx.x * blockDim.x + threadIdx.x;
    if (e < EE) atomicAdd(&g_cnt[ei[EE + e]], 1);
}
__global__ void k_dinv() {
    int i = blockIdx.x * blockDim.x + threadIdx.x;
    if (i < NN) g_dinv[i] = rsqrtf((float)g_cnt[i] + 1.0f);  // deg includes self loop
}
// exclusive prefix sum over g_cnt -> g_rowptr/g_cursor; all heavy traffic via smem
__global__ void k_scan() {
    extern __shared__ int sb[];          // [NN] counts, then [1024] partials
    int* pp = sb + NN;
    const int CH = (NN + 1023) / 1024;   // 30
    int tid = threadIdx.x;
    for (int idx = tid; idx < NN; idx += 1024) sb[idx] = g_cnt[idx];
    __syncthreads();
    int base = tid * CH;
    int s = 0;
    for (int j = 0; j < CH; j++) {
        int idx = base + j;
        if (idx < NN) s += sb[idx];
    }
    pp[tid] = s;
    __syncthreads();
    for (int off = 1; off < 1024; off <<= 1) {
        int v = (tid >= off) ? pp[tid - off] : 0;
        __syncthreads();
        pp[tid] += v;
        __syncthreads();
    }
    int total = pp[1023];
    int run = pp[tid] - s;               // exclusive prefix of this chunk
    for (int j = 0; j < CH; j++) {
        int idx = base + j;
        if (idx < NN) {
            int c = sb[idx];
            sb[idx] = run;
            run += c;
        }
    }
    __syncthreads();
    for (int idx = tid; idx < NN; idx += 1024) {
        int v = sb[idx];
        g_rowptr[idx] = v;
        g_cursor[idx] = v;
    }
    if (tid == 1023) g_rowptr[NN] = total;
}
__global__ void k_fill(const int* __restrict__ ei) {
    int e = blockIdx.x * blockDim.x + threadIdx.x;
    if (e < EE) {
        int s = ei[e];
        int d = ei[EE + e];
        int p = atomicAdd(&g_cursor[d], 1);
        g_edge[p] = make_int2(s, __float_as_int(g_dinv[s] * g_dinv[d]));
    }
}

// ---------------- FUSED [norm] -> agg(+relu) -> tensor-core GEMM ----------------
template <bool NORM, bool RELU, int ACT, bool INH, bool OUTH>
__global__ void __launch_bounds__(256)
k_fused(const void* __restrict__ in, const float* __restrict__ W,
        const float* __restrict__ bias, void* __restrict__ out) {
    extern __shared__ char smem[];
    __half* ws = (__half*)smem;
    __half* zs = (__half*)(smem + WS_BYTES);

    int tid = threadIdx.x;
    int lane = tid & 31, wrp = tid >> 5;
    int row0 = blockIdx.x * BM;
    const int2* ge = g_edge;

    // ---- stage W (fp32 -> fp16) ----
    for (int idx4 = tid; idx4 < HH * HH / 4; idx4 += 256) {
        int k = idx4 >> 5, n4 = (idx4 & 31) * 4;
        float4 v = *(const float4*)&W[(size_t)k * HH + n4];
        __half2* dst = (__half2*)&ws[k * RS + n4];
        dst[0] = __floats2half2_rn(v.x, v.y);
        dst[1] = __floats2half2_rn(v.z, v.w);
    }

    float4 m4, r4;
    if (NORM) {   // finalize instance-norm stats inline
        float4 s4 = ((const float4*)g_stats)[lane];
        float4 q4 = ((const float4*)g_stats)[32 + lane];
        const float invn = 1.0f / (float)NN;
        m4 = make_float4(s4.x * invn, s4.y * invn, s4.z * invn, s4.w * invn);
        r4 = make_float4(rsqrtf(q4.x * invn - m4.x * m4.x + EPSF),
                         rsqrtf(q4.y * invn - m4.y * m4.y + EPSF),
                         rsqrtf(q4.z * invn - m4.z * m4.z + EPSF),
                         rsqrtf(q4.w * invn - m4.w * m4.w + EPSF));
    }

    // ---- Phase A (per-warp): gather 8 rows into zs ----
    for (int mi = 0; mi < 8; mi++) {
        int m = wrp * 8 + mi;
        int i = row0 + m;
        if (i >= NN) break;
        float di = g_dinv[i];

#define LOADU(u, s)                                                        \
        float4 u = ldrow<INH>(in, (s), lane);                              \
        if (NORM) { u.x = (u.x - m4.x) * r4.x; u.y = (u.y - m4.y) * r4.y;  \
                    u.z = (u.z - m4.z) * r4.z; u.w = (u.w - m4.w) * r4.w; }\
        if (RELU) { u.x = fmaxf(u.x, 0.f); u.y = fmaxf(u.y, 0.f);          \
                    u.z = fmaxf(u.z, 0.f); u.w = fmaxf(u.w, 0.f); }

        LOADU(vs, i)
        float w = di * di;
        float p0 = w * vs.x, p1 = w * vs.y, p2 = w * vs.z, p3 = w * vs.w;
        float q0 = 0.f, q1 = 0.f, q2 = 0.f, q3 = 0.f;
        int e = g_rowptr[i], end = g_rowptr[i + 1];
        int2 h0 = ge[e], h1 = ge[e + 1], h2 = ge[e + 2], h3 = ge[e + 3];
        for (; e + 4 <= end; e += 4) {
            int2 n0 = ge[e + 4], n1 = ge[e + 5], n2 = ge[e + 6], n3 = ge[e + 7];
            float w0 = __int_as_float(h0.y), w1 = __int_as_float(h1.y);
            float w2 = __int_as_float(h2.y), w3 = __int_as_float(h3.y);
            LOADU(u0, h0.x) LOADU(u1, h1.x) LOADU(u2, h2.x) LOADU(u3, h3.x)
            p0 += w0 * u0.x; p1 += w0 * u0.y; p2 += w0 * u0.z; p3 += w0 * u0.w;
            q0 += w1 * u1.x; q1 += w1 * u1.y; q2 += w1 * u1.z; q3 += w1 * u1.w;
            p0 += w2 * u2.x; p1 += w2 * u2.y; p2 += w2 * u2.z; p3 += w2 * u2.w;
            q0 += w3 * u3.x; q1 += w3 * u3.y; q2 += w3 * u3.z; q3 += w3 * u3.w;
            h0 = n0; h1 = n1; h2 = n2; h3 = n3;
        }
        int rem = end - e;
        if (rem > 0) {
            float w0 = __int_as_float(h0.y);
            LOADU(u0, h0.x)
            p0 += w0 * u0.x; p1 += w0 * u0.y; p2 += w0 * u0.z; p3 += w0 * u0.w;
        }
        if (rem > 1) {
            float w1 = __int_as_float(h1.y);
            LOADU(u1, h1.x)
            q0 += w1 * u1.x; q1 += w1 * u1.y; q2 += w1 * u1.z; q3 += w1 * u1.w;
        }
        if (rem > 2) {
            float w2 = __int_as_float(h2.y);
            LOADU(u2, h2.x)
            p0 += w2 * u2.x; p1 += w2 * u2.y; p2 += w2 * u2.z; p3 += w2 * u2.w;
        }
#undef LOADU
        __half2* zrow = (__half2*)&zs[m * RS + lane * 4];
        zrow[0] = __floats2half2_rn(p0 + q0, p1 + q1);
        zrow[1] = __floats2half2_rn(p2 + q2, p3 + q3);
    }
    __syncthreads();   // ws + zs ready

    // ---- Phase B: warp (wrp%4) m-tile, (wrp/4) n-half; mma.m16n8k16 ----
    int m0 = (wrp & 3) * 16;
    int n0b = (wrp >> 2) * 64;
    u32 zsu = (u32)__cvta_generic_to_shared(zs);
    u32 wsu = (u32)__cvta_generic_to_shared(ws);

    float acc[8][4];
#pragma unroll
    for (int nt = 0; nt < 8; nt++)
#pragma unroll
        for (int j = 0; j < 4; j++) acc[nt][j] = 0.0f;

    u32 aaddr = zsu + (u32)((m0 + (lane & 15)) * (RS * 2)) + (u32)((lane >> 4) * 16);
    u32 baddr0 = wsu + (u32)((lane & 15) * (RS * 2));

#pragma unroll
    for (int kk = 0; kk < 8; kk++) {
        u32 a0, a1, a2, a3;
        ldsm_x4(a0, a1, a2, a3, aaddr + kk * 32);
#pragma unroll
        for (int nt = 0; nt < 8; nt++) {
            u32 b0, b1;
            ldsm_x2t(b0, b1, baddr0 + kk * 16 * (RS * 2) + (n0b + nt * 8) * 2);
            mma16816(acc[nt][0], acc[nt][1], acc[nt][2], acc[nt][3],
                     a0, a1, a2, a3, b0, b1);
        }
    }

    // ---- epilogue: bias (+tanh), store ----
    int qr = lane >> 2;
    int qc = (lane & 3) * 2;
    int r0 = row0 + m0 + qr;
#pragma unroll
    for (int nt = 0; nt < 8; nt++) {
        int c = n0b + nt * 8 + qc;
        float2 bv = *(const float2*)&bias[c];
        float o0 = acc[nt][0] + bv.x, o1 = acc[nt][1] + bv.y;
        float o2 = acc[nt][2] + bv.x, o3 = acc[nt][3] + bv.y;
        if (ACT == 1) { o0 = tanhf(o0); o1 = tanhf(o1); o2 = tanhf(o2); o3 = tanhf(o3); }
        if (OUTH) {
            if (r0 < NN)
                *(__half2*)((__half*)out + (size_t)r0 * HH + c) = __floats2half2_rn(o0, o1);
            if (r0 + 8 < NN)
                *(__half2*)((__half*)out + (size_t)(r0 + 8) * HH + c) = __floats2half2_rn(o2, o3);
        } else {
            if (r0 < NN)
                *(float2*)((float*)out + (size_t)r0 * HH + c) = make_float2(o0, o1);
            if (r0 + 8 < NN)
                *(float2*)((float*)out + (size_t)(r0 + 8) * HH + c) = make_float2(o2, o3);
        }
    }
}

// ---------------- diff conv0 (HMMA): out = [A@F | aggmesh] @ W0 + b0 -------------
// x tile [64][144] fp16: cols 0-3 = A@F gathered inline, 4-131 = aggmesh (fp32->fp16),
// 132-143 zero. W0 [132][128] fp32 -> fp16 [144][136] (rows 132-143 zero). 9 k-steps.
__global__ void __launch_bounds__(256)
k_conv0h(const float* __restrict__ mesh,   // aggmesh [N,128] fp32
         const float* __restrict__ W,      // [132][128]
         const float* __restrict__ bias,
         float* __restrict__ out) {
    extern __shared__ char smem[];
    __half* ws = (__half*)smem;
    __half* xs = (__half*)(smem + C0_WS);

    int tid = threadIdx.x, lane = tid & 31, wrp = tid >> 5;
    int row0 = blockIdx.x * BM;
    if (blockIdx.x == 0) g_stats[tid] = 0.0f;   // zero stats for upcoming in_stats

    // stage W0 (K-padded to 144)
    for (int idx4 = tid; idx4 < 144 * 32; idx4 += 256) {
        int k = idx4 >> 5, n4 = (idx4 & 31) * 4;
        float4 v = (k < KCAT) ? *(const float4*)&W[(size_t)k * HH + n4]
                              : make_float4(0.f, 0.f, 0.f, 0.f);
        __half2* dst = (__half2*)&ws[k * RS + n4];
        dst[0] = __floats2half2_rn(v.x, v.y);
        dst[1] = __floats2half2_rn(v.z, v.w);
    }
    // stage aggmesh cols 4..131
    for (int idx = tid; idx < 64 * 32; idx += 256) {
        int m = idx >> 5, c4 = (idx & 31) * 4;
        int r = row0 + m;
        float4 v = (r < NN) ? *(const float4*)&mesh[(size_t)r * HH + c4]
                            : make_float4(0.f, 0.f, 0.f, 0.f);
        __half2* dst = (__half2*)&xs[m * RS2 + 4 + c4];
        dst[0] = __floats2half2_rn(v.x, v.y);
        dst[1] = __floats2half2_rn(v.z, v.w);
    }
    // zero K-pad cols 132..143
    for (int idx = tid; idx < 64 * 6; idx += 256) {
        int m = idx / 6, j = idx - m * 6;
        ((__half2*)&xs[m * RS2 + 132])[j] = __floats2half2_rn(0.f, 0.f);
    }
    // A@F gather: 4 threads per node, shfl reduce
    {
        int m = tid >> 2, sub = tid & 3;
        int i = row0 + m;
        float a0 = 0.f, a1 = 0.f, a2 = 0.f, a3 = 0.f;
        if (i < NN) {
            float di = g_dinv[i];
            if (sub == 0) {
                float4 f = ((const float4*)g_F)[i];
                float w = di * di;
                a0 = w * f.x; a1 = w * f.y; a2 = w * f.z; a3 = w * f.w;
            }
            int e1 = g_rowptr[i + 1];
            for (int e = g_rowptr[i] + sub; e < e1; e += 4) {
                int2 ed = g_edge[e];
                float ww = __int_as_float(ed.y);
                float4 u = ((const float4*)g_F)[ed.x];
                a0 += ww * u.x; a1 += ww * u.y; a2 += ww * u.z; a3 += ww * u.w;
            }
        }
        a0 += __shfl_xor_sync(~0u, a0, 1); a1 += __shfl_xor_sync(~0u, a1, 1);
        a2 += __shfl_xor_sync(~0u, a2, 1); a3 += __shfl_xor_sync(~0u, a3, 1);
        a0 += __shfl_xor_sync(~0u, a0, 2); a1 += __shfl_xor_sync(~0u, a1, 2);
        a2 += __shfl_xor_sync(~0u, a2, 2); a3 += __shfl_xor_sync(~0u, a3, 2);
        if (sub == 0) {
            __half2* dst = (__half2*)&xs[m * RS2];
            dst[0] = __floats2half2_rn(a0, a1);
            dst[1] = __floats2half2_rn(a2, a3);
        }
    }
    __syncthreads();

    // MMA: 9 k-steps
    int m0 = (wrp & 3) * 16;
    int n0b = (wrp >> 2) * 64;
    u32 xsu = (u32)__cvta_generic_to_shared(xs);
    u32 wsu = (u32)__cvta_generic_to_shared(ws);
    float acc[8][4];
#pragma unroll
    for (int nt = 0; nt < 8; nt++)
#pragma unroll
        for (int j = 0; j < 4; j++) acc[nt][j] = 0.0f;

    u32 aaddr = xsu + (u32)((m0 + (lane & 15)) * (RS2 * 2)) + (u32)((lane >> 4) * 16);
    u32 baddr0 = wsu + (u32)((lane & 15) * (RS * 2));
#pragma unroll
    for (int kk = 0; kk < 9; kk++) {
        u32 a0, a1, a2, a3;
        ldsm_x4(a0, a1, a2, a3, aaddr + kk * 32);
#pragma unroll
        for (int nt = 0; nt < 8; nt++) {
            u32 b0, b1;
            ldsm_x2t(b0, b1, baddr0 + kk * 16 * (RS * 2) + (n0b + nt * 8) * 2);
            mma16816(acc[nt][0], acc[nt][1], acc[nt][2], acc[nt][3],
                     a0, a1, a2, a3, b0, b1);
        }
    }

    int qr = lane >> 2, qc = (lane & 3) * 2;
    int r0 = row0 + m0 + qr;
#pragma unroll
    for (int nt = 0; nt < 8; nt++) {
        int c = n0b + nt * 8 + qc;
        float2 bv = *(const float2*)&bias[c];
        if (r0 < NN)
            *(float2*)&out[(size_t)r0 * HH + c] = make_float2(acc[nt][0] + bv.x, acc[nt][1] + bv.y);
        if (r0 + 8 < NN)
            *(float2*)&out[(size_t)(r0 + 8) * HH + c] = make_float2(acc[nt][2] + bv.x, acc[nt][3] + bv.y);
    }
}

// ---------------- standalone 128-col aggregation (aggmesh, once) -----------------
__global__ void k_agg128(const float* __restrict__ in, float* __restrict__ out,
                         int ostride, int ooff) {
    int i = blockIdx.x;
    int c = threadIdx.x;
    float di = g_dinv[i];
    float acc = di * di * in[(size_t)i * HH + c];
    int e = g_rowptr[i], end = g_rowptr[i + 1];
    for (; e + 2 <= end; e += 2) {
        int2 e0 = g_edge[e], e1 = g_edge[e + 1];
        acc += __int_as_float(e0.y) * in[(size_t)e0.x * HH + c];
        acc += __int_as_float(e1.y) * in[(size_t)e1.x * HH + c];
    }
    for (; e < end; e++) {
        int2 e0 = g_edge[e];
        acc += __int_as_float(e0.y) * in[(size_t)e0.x * HH + c];
    }
    out[(size_t)i * ostride + ooff + c] = acc;
}

// 8-column aggregate of meshfield -> g_small
__global__ void k_agg8(const float* __restrict__ in) {
    int i = blockIdx.x * blockDim.x + threadIdx.x;
    if (i >= NN) return;
    float di = g_dinv[i];
    const float4* inv = (const float4*)in;
    float4 u0 = inv[i * 2], u1 = inv[i * 2 + 1];
    float w = di * di;
    float a0 = w * u0.x, a1 = w * u0.y, a2 = w * u0.z, a3 = w * u0.w;
    float a4 = w * u1.x, a5 = w * u1.y, a6 = w * u1.z, a7 = w * u1.w;
    for (int e = g_rowptr[i]; e < g_rowptr[i + 1]; e++) {
        int2 ed = g_edge[e];
        float ww = __int_as_float(ed.y);
        float4 b0 = inv[ed.x * 2], b1 = inv[ed.x * 2 + 1];
        a0 += ww * b0.x; a1 += ww * b0.y; a2 += ww * b0.z; a3 += ww * b0.w;
        a4 += ww * b1.x; a5 += ww * b1.y; a6 += ww * b1.z; a7 += ww * b1.w;
    }
    float4* ov = (float4*)g_small;
    ov[i * 2]     = make_float4(a0, a1, a2, a3);
    ov[i * 2 + 1] = make_float4(a4, a5, a6, a7);
}

// ---------------- fp32 GEMM (mesh conv0, K=8): out = x @ W + bias ----------------
__global__ void __launch_bounds__(256)
k_gemm128(const float* __restrict__ x, int K,
          const float* __restrict__ W, const float* __restrict__ bias,
          float* __restrict__ out) {
    __shared__ float xs[64 * KC];
    __shared__ float wsf[KC * HH];
    int tid = threadIdx.x;
    if (blockIdx.x == 0) g_stats[tid] = 0.0f;
    int row0 = blockIdx.x * 64;
    int valid = NN - row0; if (valid > 64) valid = 64;
    int tx = tid & 31, ty = tid >> 5;

    ull acc01[8], acc23[8];
#pragma unroll
    for (int i = 0; i < 8; i++) { acc01[i] = 0ull; acc23[i] = 0ull; }

    for (int k0 = 0; k0 < K; k0 += KC) {
        int kc = K - k0; if (kc > KC) kc = KC;
        __syncthreads();
        {
            const float4* Wv = (const float4*)(W + (size_t)k0 * HH);
            float4* wv = (float4*)wsf;
            for (int idx = tid; idx < kc * 32; idx += 256) wv[idx] = Wv[idx];
        }
        {
            const float* xg = x + (size_t)row0 * K + k0;
            for (int idx = tid; idx < valid * kc; idx += 256) {
                int r = idx / kc, j = idx - r * kc;
                xs[r * KC + j] = xg[(size_t)r * K + j];
            }
        }
        __syncthreads();
        const float* xsr = xs + (ty * 8) * KC;
        for (int j = 0; j < kc; j++) {
            float4 b = *(const float4*)&wsf[j * HH + tx * 4];
            ull b01 = pk2(b.x, b.y), b23 = pk2(b.z, b.w);
#pragma unroll
            for (int i = 0; i < 8; i++) {
                float a = xsr[i * KC + j];
                ull ap = pk2(a, a);
                acc01[i] = ffma2(ap, b01, acc01[i]);
                acc23[i] = ffma2(ap, b23, acc23[i]);
            }
        }
    }
    float4 bv = *(const float4*)&bias[tx * 4];
#pragma unroll
    for (int i = 0; i < 8; i++) {
        int r = ty * 8 + i;
        if (row0 + r < NN) {
            float o0, o1, o2, o3;
            upk2(o0, o1, acc01[i]); upk2(o2, o3, acc23[i]);
            o0 += bv.x; o1 += bv.y; o2 += bv.z; o3 += bv.w;
            *(float4*)&out[(size_t)(row0 + r) * HH + tx * 4] = make_float4(o0, o1, o2, o3);
        }
    }
}

// small GEMM: g_h4[N,4] = x_half[N,128] @ W[128,4]
__global__ void k_gemm_to4(const __half* __restrict__ x, const float* __restrict__ W) {
    __shared__ float xs[32 * 129];
    __shared__ float wsf[HH * 4];
    int tid = threadIdx.x;
    int row0 = blockIdx.x * 32;
    int valid = NN - row0; if (valid > 32) valid = 32;
    for (int idx = tid; idx < HH * 4; idx += 128) wsf[idx] = W[idx];
    for (int idx = tid; idx < valid * HH; idx += 128) {
        int r = idx >> 7, k = idx & 127;
        xs[r * 129 + k] = __half2float(x[(size_t)row0 * HH + idx]);
    }
    __syncthreads();
    int r = tid >> 2, c = tid & 3;
    if (row0 + r < NN) {
        float acc = 0.0f;
#pragma unroll 8
        for (int k = 0; k < HH; k++) acc += xs[r * 129 + k] * wsf[k * 4 + c];
        g_h4[(size_t)(row0 + r) * 4 + c] = acc;
    }
}

// ---------------- instance norm stats (per-channel over nodes) ----------------
__global__ void k_in_stats(const float* __restrict__ x) {
    int c = threadIdx.x;
    float s = 0.0f, q = 0.0f;
    for (int r = blockIdx.x; r < NN; r += gridDim.x) {
        float v = x[(size_t)r * HH + c];
        s += v; q += v * v;
    }
    atomicAdd(&g_stats[c], s);
    atomicAdd(&g_stats[HH + c], q);
}

// ---------------- recurrent step tail ----------------
__global__ void k_copyF0(const float* __restrict__ F0) {
    int i = blockIdx.x * blockDim.x + threadIdx.x;
    if (i < NN * NFF) g_F[i] = F0[i];
}
__global__ void k_step_final(const float* __restrict__ b9, float* __restrict__ out, int t) {
    int i = blockIdx.x * blockDim.x + threadIdx.x;
    if (i >= NN) return;
    float di = g_dinv[i];
    const float4* h4 = (const float4*)g_h4;
    float4 v = h4[i];
    float w = di * di;
    float a0 = b9[0] + w * v.x, a1 = b9[1] + w * v.y;
    float a2 = b9[2] + w * v.z, a3 = b9[3] + w * v.w;
    for (int e = g_rowptr[i]; e < g_rowptr[i + 1]; e++) {
        int2 ed = g_edge[e];
        float ww = __int_as_float(ed.y);
        float4 u = h4[ed.x];
        a0 += ww * u.x; a1 += ww * u.y; a2 += ww * u.z; a3 += ww * u.w;
    }
    float d0 = tanhf(a0), d1 = tanhf(a1), d2 = tanhf(a2), d3 = tanhf(a3);
    float4 f = ((float4*)g_F)[i];
    float n0 = tanhf(f.x + DTF * d0), n1 = tanhf(f.y + DTF * d1);
    float n2 = tanhf(f.z + DTF * d2), n3 = tanhf(f.w + DTF * d3);
    ((float4*)g_F)[i] = make_float4(n0, n1, n2, n3);
    int ob = i * TT * NFF + t * NFF;
    out[ob + 0] = n0; out[ob + 1] = n1; out[ob + 2] = n2; out[ob + 3] = n3;
    int ob2 = NN * TT * NFF + ob;
    out[ob2 + 0] = d0; out[ob2 + 1] = d1; out[ob2 + 2] = d2; out[ob2 + 3] = d3;
}

// fused-kernel variants
#define KF_NORM  k_fused<true,  true,  0, false, true>   // fp32 in (norm+relu) -> half out
#define KF_MID   k_fused<false, true,  0, true,  true>   // half in (relu)      -> half out
#define KF_TANH  k_fused<false, false, 1, true,  false>  // half in             -> fp32 tanh out

// ---------------- host orchestration ----------------
extern "C" void kernel_launch(void* const* d_in, const int* in_sizes, int n_in,
                              void* d_out, int out_size) {
    const float* F0        = (const float*)d_in[0];
    const int*   ei        = (const int*)d_in[1];
    const float* meshfield = (const float*)d_in[2];
    int w = (n_in >= 16 && in_sizes[3] == 1) ? 4 : 3;  // skip scalar n_time if present
    const float* mesh_W0 = (const float*)d_in[w + 0];
    const float* mesh_b0 = (const float*)d_in[w + 1];
    const float* mesh_Wh = (const float*)d_in[w + 2];
    const float* mesh_bh = (const float*)d_in[w + 3];
    const float* mesh_W9 = (const float*)d_in[w + 4];
    const float* mesh_b9 = (const float*)d_in[w + 5];
    const float* diff_W0 = (const float*)d_in[w + 6];
    const float* diff_b0 = (const float*)d_in[w + 7];
    const float* diff_Wh = (const float*)d_in[w + 8];
    const float* diff_bh = (const float*)d_in[w + 9];
    const float* diff_W9 = (const float*)d_in[w + 10];
    const float* diff_b9 = (const float*)d_in[w + 11];
    float* out = (float*)d_out;

    float *px, *pz, *pxcat, *psmall;
    __half *ph0, *ph1;
    cudaGetSymbolAddress((void**)&px, g_x);
    cudaGetSymbolAddress((void**)&pz, g_z);
    cudaGetSymbolAddress((void**)&pxcat, g_xcat);
    cudaGetSymbolAddress((void**)&psmall, g_small);
    cudaGetSymbolAddress((void**)&ph0, g_xh0);
    cudaGetSymbolAddress((void**)&ph1, g_xh1);

    cudaFuncSetAttribute(KF_NORM, cudaFuncAttributeMaxDynamicSharedMemorySize, FUSED_SMEM);
    cudaFuncSetAttribute(KF_MID,  cudaFuncAttributeMaxDynamicSharedMemorySize, FUSED_SMEM);
    cudaFuncSetAttribute(KF_TANH, cudaFuncAttributeMaxDynamicSharedMemorySize, FUSED_SMEM);
    cudaFuncSetAttribute(k_conv0h, cudaFuncAttributeMaxDynamicSharedMemorySize, CONV0_SMEM);
    cudaFuncSetAttribute(k_scan,   cudaFuncAttributeMaxDynamicSharedMemorySize, SCAN_SMEM);

    const int GB = (NN + 63) / 64;
    const int FB = (NN + BM - 1) / BM;

    // --- graph normalization + CSR (weights precomputed) ---
    k_zero_cnt<<<(NN + 255) / 256, 256>>>();
    k_count<<<(EE + 255) / 256, 256>>>(ei);
    k_dinv<<<(NN + 255) / 256, 256>>>();
    k_scan<<<1, 1024, SCAN_SMEM>>>();
    k_fill<<<(EE + 255) / 256, 256>>>(ei);

    // --- mesh descriptor block ---
    k_agg8<<<(NN + 127) / 128, 128>>>(meshfield);                      // A@meshfield (8 cols)
    k_gemm128<<<GB, 256>>>(psmall, NMM, mesh_W0, mesh_b0, px);         // conv0 (+zero stats)
    k_in_stats<<<512, HH>>>(px);
    {
        KF_NORM<<<FB, 256, FUSED_SMEM>>>(px, mesh_Wh, mesh_bh, ph0);
        __half* cur = ph0; __half* nxt = ph1;
        for (int l = 1; l < DMID; l++) {
            KF_MID<<<FB, 256, FUSED_SMEM>>>(cur, mesh_Wh + (size_t)l * HH * HH,
                                            mesh_bh + (size_t)l * HH, nxt);
            __half* t2 = cur; cur = nxt; nxt = t2;
        }
        KF_TANH<<<FB, 256, FUSED_SMEM>>>(cur, mesh_W9, mesh_b9, pz);   // conv9+tanh (fp32)
        k_agg128<<<NN, HH>>>(pz, pxcat, HH, 0);                        // aggmesh [N,128]
    }

    // --- recurrent differentiator ---
    k_copyF0<<<(NN * NFF + 255) / 256, 256>>>(F0);
    for (int t = 0; t < TT; t++) {
        k_conv0h<<<FB, 256, CONV0_SMEM>>>(pxcat, diff_W0, diff_b0, px); // conv0 incl A@F (+zero stats)
        k_in_stats<<<512, HH>>>(px);
        KF_NORM<<<FB, 256, FUSED_SMEM>>>(px, diff_Wh, diff_bh, ph0);
        __half* cur = ph0; __half* nxt = ph1;
        for (int l = 1; l < DMID; l++) {
            KF_MID<<<FB, 256, FUSED_SMEM>>>(cur, diff_Wh + (size_t)l * HH * HH,
                                            diff_bh + (size_t)l * HH, nxt);
            __half* t2 = cur; cur = nxt; nxt = t2;
        }
        k_gemm_to4<<<(NN + 31) / 32, 128>>>(cur, diff_W9);             // half x @ W9 -> h4
        k_step_final<<<(NN + 127) / 128, 128>>>(diff_b9, out, t);      // A@h4+b9, Euler, write
    }
    (void)out_size;
}